// round 2
// baseline (speedup 1.0000x reference)
#include <cuda_runtime.h>
#include <math.h>

#define D_DIM 256
#define K_CB  1024
#define N_VEC_MAX 65536

#define BM 128
#define BN 128
#define BK 32
#define NT 256

// ---- scratch (no allocations allowed) ----
__device__ int          g_idx[N_VEC_MAX];
__device__ float        g_enorm[K_CB];
__device__ unsigned int g_counts[K_CB];
__device__ double       g_sumsq;

// ---------------------------------------------------------------------------
// K0: zero accumulators
// ---------------------------------------------------------------------------
__global__ void vq_zero_kernel() {
    int t = threadIdx.x;
    if (t < K_CB) g_counts[t] = 0u;
    if (t == 0)   g_sumsq = 0.0;
}

// ---------------------------------------------------------------------------
// K1: codebook row norms  g_enorm[k] = sum_d e[k][d]^2   (one warp per row)
// (order-insensitive: B ~ 8e-5, its rounding noise ~1e-12 never decides)
// ---------------------------------------------------------------------------
__global__ void vq_enorm_kernel(const float* __restrict__ e) {
    int w    = (blockIdx.x * blockDim.x + threadIdx.x) >> 5;  // row id 0..1023
    int lane = threadIdx.x & 31;
    const float4* e4 = (const float4*)(e + (size_t)w * D_DIM);
    float s = 0.f;
    #pragma unroll
    for (int q = 0; q < 2; q++) {
        float4 v = e4[lane + q * 32];
        s += v.x * v.x + v.y * v.y + v.z * v.z + v.w * v.w;
    }
    #pragma unroll
    for (int m = 16; m; m >>= 1) s += __shfl_xor_sync(0xffffffffu, s, m);
    if (lane == 0) g_enorm[w] = s;
}

// ---------------------------------------------------------------------------
// K2: fused distance-GEMM + argmin, replicating the reference's fp32 rounding:
//   M[n][k] accumulated as a SERIAL ascending-d fma chain (Eigen/cuBLAS order)
//   dist    = fl( fl(A[n] + B[k]) - 2*M )   (double rounding, no contraction)
//   argmin tie-break: lowest index (jnp.argmin first occurrence)
// A[n]'s low bits are argmin-invariant (uniform grid shift), so A is computed
// in-kernel from the resident x tile in any order.
// ---------------------------------------------------------------------------
__global__ void __launch_bounds__(NT, 1) vq_argmin_kernel(
    const float* __restrict__ x, const float* __restrict__ e)
{
    extern __shared__ float smem[];
    float* xs = smem;                   // [256][128]
    float* es = smem + D_DIM * BM;      // [2][32][128], xor-swizzled columns
    __shared__ float a_row[BM];         // per-row ||x||^2

    const int t  = threadIdx.x;
    const int tx = t & 15;
    const int ty = t >> 4;
    const size_t rb = (size_t)blockIdx.x * BM;

    // ---- load x tile transposed: xs[d][m] = x[rb+m][d]
    {
        const float4* x4 = (const float4*)(x + rb * D_DIM);
        #pragma unroll
        for (int it = 0; it < (BM * (D_DIM / 4)) / NT; it++) {
            int i  = t + it * NT;
            int m  = i & (BM - 1);
            int d4 = i >> 7;
            float4 v = x4[(size_t)m * (D_DIM / 4) + d4];
            xs[(d4 * 4 + 0) * BM + m] = v.x;
            xs[(d4 * 4 + 1) * BM + m] = v.y;
            xs[(d4 * 4 + 2) * BM + m] = v.z;
            xs[(d4 * 4 + 3) * BM + m] = v.w;
        }
    }

    const int kk = t >> 3;   // 0..31  (k sub-row)
    const int dd = t & 7;    // 0..7   (float4 column within BK chunk)
    const float4* e4 = (const float4*)e;

    float4 ev[4];
    // prologue: chunk 0 (kt=0, dc=0) -> buf 0
    #pragma unroll
    for (int q = 0; q < 4; q++)
        ev[q] = e4[(size_t)(q * 32 + kk) * (D_DIM / 4) + dd];
    #pragma unroll
    for (int q = 0; q < 4; q++) {
        float vv[4] = {ev[q].x, ev[q].y, ev[q].z, ev[q].w};
        #pragma unroll
        for (int j = 0; j < 4; j++) {
            int d_l = dd * 4 + j;
            es[d_l * BN + ((q * 32 + kk) ^ (d_l & 28))] = vv[j];
        }
    }
    __syncthreads();

    // ---- per-row ||x||^2 (order-free; 4 partial sums for ILP)
    if (t < BM) {
        float s0 = 0.f, s1 = 0.f, s2 = 0.f, s3 = 0.f;
        #pragma unroll 8
        for (int d = 0; d < D_DIM; d += 4) {
            float v0 = xs[(d + 0) * BM + t];
            float v1 = xs[(d + 1) * BM + t];
            float v2 = xs[(d + 2) * BM + t];
            float v3 = xs[(d + 3) * BM + t];
            s0 = fmaf(v0, v0, s0); s1 = fmaf(v1, v1, s1);
            s2 = fmaf(v2, v2, s2); s3 = fmaf(v3, v3, s3);
        }
        a_row[t] = (s0 + s1) + (s2 + s3);
    }
    // a_row is first read in the dc==7 fold of c=7; the per-iteration
    // __syncthreads at c=0..6 order the write before any read.

    float best_key[8];
    int   best_k[8];
    #pragma unroll
    for (int i = 0; i < 8; i++) { best_key[i] = 3.4e38f; best_k[i] = 0x7fffffff; }

    float acc[8][8];
    #pragma unroll
    for (int i = 0; i < 8; i++)
        #pragma unroll
        for (int j = 0; j < 8; j++) acc[i][j] = 0.f;

    for (int c = 0; c < 64; c++) {            // 8 k-tiles x 8 d-chunks
        const int kt = c >> 3, dc = c & 7, buf = c & 1;

        // prefetch next chunk into registers
        if (c + 1 < 64) {
            int nkt = (c + 1) >> 3, ndc = (c + 1) & 7;
            #pragma unroll
            for (int q = 0; q < 4; q++)
                ev[q] = e4[(size_t)(nkt * 128 + q * 32 + kk) * (D_DIM / 4)
                           + ndc * 8 + dd];
        }

        // ---- compute: 32 rank-1 updates (serial ascending-d fma chains)
        const float* xs_d = xs + (dc * 32) * BM;
        const float* es_d = es + buf * (BK * BN);
        #pragma unroll 4
        for (int d = 0; d < 32; d++) {
            float4 a0 = *(const float4*)(xs_d + d * BM + ty * 4);
            float4 a1 = *(const float4*)(xs_d + d * BM + 64 + ty * 4);
            const int sw = d & 28;
            float4 b0 = *(const float4*)(es_d + d * BN + ((tx * 4) ^ sw));
            float4 b1 = *(const float4*)(es_d + d * BN + (64 + ((tx * 4) ^ sw)));
            float a[8] = {a0.x, a0.y, a0.z, a0.w, a1.x, a1.y, a1.z, a1.w};
            float b[8] = {b0.x, b0.y, b0.z, b0.w, b1.x, b1.y, b1.z, b1.w};
            #pragma unroll
            for (int i = 0; i < 8; i++)
                #pragma unroll
                for (int j = 0; j < 8; j++)
                    acc[i][j] = fmaf(a[i], b[j], acc[i][j]);
        }

        // ---- fold argmin once a k-tile's full dot is accumulated
        if (dc == 7) {
            const int kb = kt * 128;
            float en[8];
            #pragma unroll
            for (int j = 0; j < 8; j++) {
                int cc = (j < 4) ? (tx * 4 + j) : (64 + tx * 4 + (j - 4));
                en[j] = g_enorm[kb + cc];
            }
            #pragma unroll
            for (int i = 0; i < 8; i++) {
                int   r = (i < 4) ? (ty * 4 + i) : (64 + ty * 4 + (i - 4));
                float A = a_row[r];
                float bk = 3.4e38f; int bc = 0x7fffffff;
                #pragma unroll
                for (int j = 0; j < 8; j++) {
                    int cc = (j < 4) ? (tx * 4 + j) : (64 + tx * 4 + (j - 4));
                    // key = fl( fl(A + B) - 2*M ), intrinsics block contraction
                    float tsum = __fadd_rn(A, en[j]);
                    float m2   = __fmul_rn(2.0f, acc[i][j]);
                    float key  = __fadd_rn(tsum, -m2);
                    if (key < bk) { bk = key; bc = kb + cc; }
                    acc[i][j] = 0.f;
                }
                #pragma unroll
                for (int m = 8; m; m >>= 1) {
                    float ok = __shfl_xor_sync(0xffffffffu, bk, m);
                    int   oc = __shfl_xor_sync(0xffffffffu, bc, m);
                    if (ok < bk || (ok == bk && oc < bc)) { bk = ok; bc = oc; }
                }
                if (bk < best_key[i] || (bk == best_key[i] && bc < best_k[i])) {
                    best_key[i] = bk; best_k[i] = bc;
                }
            }
        }

        // ---- STS next chunk into the other buffer
        if (c + 1 < 64) {
            float* esn = es + ((c + 1) & 1) * (BK * BN);
            #pragma unroll
            for (int q = 0; q < 4; q++) {
                float vv[4] = {ev[q].x, ev[q].y, ev[q].z, ev[q].w};
                #pragma unroll
                for (int j = 0; j < 4; j++) {
                    int d_l = dd * 4 + j;
                    esn[d_l * BN + ((q * 32 + kk) ^ (d_l & 28))] = vv[j];
                }
            }
        }
        __syncthreads();
    }

    if (tx == 0) {
        #pragma unroll
        for (int i = 0; i < 8; i++) {
            int r = (i < 4) ? (ty * 4 + i) : (64 + ty * 4 + (i - 4));
            g_idx[rb + r] = best_k[i];
        }
    }
}

// ---------------------------------------------------------------------------
// K3: gather + straight-through output + MSE partials + histogram
//   one block per vector (256 threads = D)
// ---------------------------------------------------------------------------
__global__ void vq_gather_kernel(const float* __restrict__ x,
                                 const float* __restrict__ e,
                                 float* __restrict__ out)
{
    __shared__ float red[8];
    const int v = blockIdx.x;
    const int k = g_idx[v];
    const int d = threadIdx.x;
    const size_t off = (size_t)v * D_DIM + d;
    float xv = x[off];
    float q  = e[(size_t)k * D_DIM + d];
    float diff = __fadd_rn(q, -xv);
    out[off] = __fadd_rn(xv, diff);    // x + (q - x), matches reference rounding
    float s = diff * diff;
    #pragma unroll
    for (int m = 16; m; m >>= 1) s += __shfl_xor_sync(0xffffffffu, s, m);
    int lane = d & 31, w = d >> 5;
    if (lane == 0) red[w] = s;
    __syncthreads();
    if (d < 8) {
        float t2 = red[d];
        #pragma unroll
        for (int m = 4; m; m >>= 1) t2 += __shfl_xor_sync(0x000000ffu, t2, m);
        if (d == 0) {
            atomicAdd(&g_sumsq, (double)t2);
            atomicAdd(&g_counts[k], 1u);
        }
    }
}

// ---------------------------------------------------------------------------
// K4: finalize loss + perplexity
// ---------------------------------------------------------------------------
__global__ void vq_finalize_kernel(float* __restrict__ out_scalars, int n_vec)
{
    __shared__ float red[32];
    const int t = threadIdx.x;           // 1024 threads
    float p = (float)g_counts[t] / (float)n_vec;
    float s = p * logf(p + 1e-10f);
    #pragma unroll
    for (int m = 16; m; m >>= 1) s += __shfl_xor_sync(0xffffffffu, s, m);
    int lane = t & 31, w = t >> 5;
    if (lane == 0) red[w] = s;
    __syncthreads();
    if (t < 32) {
        float t2 = red[t];
        #pragma unroll
        for (int m = 16; m; m >>= 1) t2 += __shfl_xor_sync(0xffffffffu, t2, m);
        if (t == 0) {
            double mse = g_sumsq / ((double)n_vec * (double)D_DIM);
            out_scalars[0] = (float)(1.25 * mse);   // q_latent + 0.25*e_latent
            out_scalars[1] = expf(-t2);
        }
    }
}

// ---------------------------------------------------------------------------
extern "C" void kernel_launch(void* const* d_in, const int* in_sizes, int n_in,
                              void* d_out, int out_size)
{
    const float* x = (const float*)d_in[0];   // [64,32,32,256] f32
    const float* e = (const float*)d_in[1];   // [1024,256] f32
    float* out = (float*)d_out;

    const int n_vec = in_sizes[0] / D_DIM;    // 65536

    static const int kSmem = (D_DIM * BM + 2 * BK * BN) * (int)sizeof(float); // 160 KB
    cudaFuncSetAttribute(vq_argmin_kernel,
                         cudaFuncAttributeMaxDynamicSharedMemorySize, kSmem);

    vq_zero_kernel<<<1, K_CB>>>();
    vq_enorm_kernel<<<K_CB / 8, 256>>>(e);
    vq_argmin_kernel<<<n_vec / BM, NT, kSmem>>>(x, e);
    vq_gather_kernel<<<n_vec, D_DIM>>>(x, e, out);
    vq_finalize_kernel<<<1, K_CB>>>(out + (size_t)n_vec * D_DIM, n_vec);
}

// round 3
// speedup vs baseline: 1.1198x; 1.1198x over previous
#include <cuda_runtime.h>
#include <math.h>

#define D_DIM 256
#define K_CB  1024

#define BM 128
#define BN 128
#define BK 32
#define NT 256

// ---- scratch (no allocations allowed) ----
__device__ float        g_enorm[K_CB];
__device__ unsigned int g_counts[K_CB];
__device__ double       g_sumsq;

// ---------------------------------------------------------------------------
// packed f32x2 helpers (PTX-only pipe; per-lane IEEE RN identical to fmaf)
// ---------------------------------------------------------------------------
__device__ __forceinline__ unsigned long long pk2(float lo, float hi) {
    unsigned long long r;
    asm("mov.b64 %0, {%1, %2};" : "=l"(r) : "f"(lo), "f"(hi));
    return r;
}
__device__ __forceinline__ void upk2(float& lo, float& hi, unsigned long long v) {
    asm("mov.b64 {%0, %1}, %2;" : "=f"(lo), "=f"(hi) : "l"(v));
}
__device__ __forceinline__ void fma2(unsigned long long& d,
                                     unsigned long long a,
                                     unsigned long long b) {
    asm("fma.rn.f32x2 %0, %1, %2, %0;" : "+l"(d) : "l"(a), "l"(b));
}

// ---------------------------------------------------------------------------
// K0: zero accumulators
// ---------------------------------------------------------------------------
__global__ void vq_zero_kernel() {
    int t = threadIdx.x;
    if (t < K_CB) g_counts[t] = 0u;
    if (t == 0)   g_sumsq = 0.0;
}

// ---------------------------------------------------------------------------
// K1: codebook row norms  g_enorm[k] = sum_d e[k][d]^2   (one warp per row)
// ---------------------------------------------------------------------------
__global__ void vq_enorm_kernel(const float* __restrict__ e) {
    int w    = (blockIdx.x * blockDim.x + threadIdx.x) >> 5;  // row id 0..1023
    int lane = threadIdx.x & 31;
    const float4* e4 = (const float4*)(e + (size_t)w * D_DIM);
    float s = 0.f;
    #pragma unroll
    for (int q = 0; q < 2; q++) {
        float4 v = e4[lane + q * 32];
        s += v.x * v.x + v.y * v.y + v.z * v.z + v.w * v.w;
    }
    #pragma unroll
    for (int m = 16; m; m >>= 1) s += __shfl_xor_sync(0xffffffffu, s, m);
    if (lane == 0) g_enorm[w] = s;
}

// ---------------------------------------------------------------------------
// K2: fused distance-GEMM (f32x2) + argmin + gather/ST output + MSE + hist.
//   M[n][k]: SERIAL ascending-d fma chain per element (f32x2 lanes preserve it)
//   dist = fl( fl(A[n] + B[k]) - 2*M ),  tie-break lowest index.
//   Epilogue: all tx lanes hold the block-row argmin -> cooperative row
//   stream: out = x + (q - x), diff^2 partials, histogram atomics.
// ---------------------------------------------------------------------------
__global__ void __launch_bounds__(NT, 1) vq_argmin_fused_kernel(
    const float* __restrict__ x, const float* __restrict__ e,
    float* __restrict__ out)
{
    extern __shared__ float smem[];
    float* xs = smem;                   // [256][128]
    float* es = smem + D_DIM * BM;      // [2][32][128], xor-swizzled columns
    __shared__ float a_row[BM];         // per-row ||x||^2
    __shared__ float redm[8];

    const int t  = threadIdx.x;
    const int tx = t & 15;
    const int ty = t >> 4;
    const size_t rb = (size_t)blockIdx.x * BM;

    // ---- load x tile transposed: xs[d][m] = x[rb+m][d]
    {
        const float4* x4 = (const float4*)(x + rb * D_DIM);
        #pragma unroll
        for (int it = 0; it < (BM * (D_DIM / 4)) / NT; it++) {
            int i  = t + it * NT;
            int m  = i & (BM - 1);
            int d4 = i >> 7;
            float4 v = x4[(size_t)m * (D_DIM / 4) + d4];
            xs[(d4 * 4 + 0) * BM + m] = v.x;
            xs[(d4 * 4 + 1) * BM + m] = v.y;
            xs[(d4 * 4 + 2) * BM + m] = v.z;
            xs[(d4 * 4 + 3) * BM + m] = v.w;
        }
    }

    const int kk = t >> 3;   // 0..31  (k sub-row)
    const int dd = t & 7;    // 0..7   (float4 column within BK chunk)
    const float4* e4 = (const float4*)e;

    float4 ev[4];
    // prologue: chunk 0 (kt=0, dc=0) -> buf 0
    #pragma unroll
    for (int q = 0; q < 4; q++)
        ev[q] = e4[(size_t)(q * 32 + kk) * (D_DIM / 4) + dd];
    #pragma unroll
    for (int q = 0; q < 4; q++) {
        float vv[4] = {ev[q].x, ev[q].y, ev[q].z, ev[q].w};
        #pragma unroll
        for (int j = 0; j < 4; j++) {
            int d_l = dd * 4 + j;
            es[d_l * BN + ((q * 32 + kk) ^ (d_l & 28))] = vv[j];
        }
    }
    __syncthreads();

    // ---- per-row ||x||^2 (order-free; argmin-invariant low bits)
    if (t < BM) {
        float s0 = 0.f, s1 = 0.f, s2 = 0.f, s3 = 0.f;
        #pragma unroll 8
        for (int d = 0; d < D_DIM; d += 4) {
            float v0 = xs[(d + 0) * BM + t];
            float v1 = xs[(d + 1) * BM + t];
            float v2 = xs[(d + 2) * BM + t];
            float v3 = xs[(d + 3) * BM + t];
            s0 = fmaf(v0, v0, s0); s1 = fmaf(v1, v1, s1);
            s2 = fmaf(v2, v2, s2); s3 = fmaf(v3, v3, s3);
        }
        a_row[t] = (s0 + s1) + (s2 + s3);
    }
    // a_row first read at the c=7 fold; per-iter __syncthreads order it.

    float best_key[8];
    int   best_k[8];
    #pragma unroll
    for (int i = 0; i < 8; i++) { best_key[i] = 3.4e38f; best_k[i] = 0x7fffffff; }

    // packed accumulators: acc2[i][jp] holds cols (pair along j)
    unsigned long long acc2[8][4];
    #pragma unroll
    for (int i = 0; i < 8; i++)
        #pragma unroll
        for (int jp = 0; jp < 4; jp++) acc2[i][jp] = 0ull;

    for (int c = 0; c < 64; c++) {            // 8 k-tiles x 8 d-chunks
        const int kt = c >> 3, dc = c & 7, buf = c & 1;

        // prefetch next chunk into registers
        if (c + 1 < 64) {
            int nkt = (c + 1) >> 3, ndc = (c + 1) & 7;
            #pragma unroll
            for (int q = 0; q < 4; q++)
                ev[q] = e4[(size_t)(nkt * 128 + q * 32 + kk) * (D_DIM / 4)
                           + ndc * 8 + dd];
        }

        // ---- compute: 32 rank-1 updates, packed f32x2 (2 FMA/instr)
        const float* xs_d = xs + (dc * 32) * BM;
        const float* es_d = es + buf * (BK * BN);
        #pragma unroll 4
        for (int d = 0; d < 32; d++) {
            float4 a0 = *(const float4*)(xs_d + d * BM + ty * 4);
            float4 a1 = *(const float4*)(xs_d + d * BM + 64 + ty * 4);
            const int sw = d & 28;
            float4 b0 = *(const float4*)(es_d + d * BN + ((tx * 4) ^ sw));
            float4 b1 = *(const float4*)(es_d + d * BN + (64 + ((tx * 4) ^ sw)));
            unsigned long long ap[8], bp[4];
            ap[0] = pk2(a0.x, a0.x); ap[1] = pk2(a0.y, a0.y);
            ap[2] = pk2(a0.z, a0.z); ap[3] = pk2(a0.w, a0.w);
            ap[4] = pk2(a1.x, a1.x); ap[5] = pk2(a1.y, a1.y);
            ap[6] = pk2(a1.z, a1.z); ap[7] = pk2(a1.w, a1.w);
            bp[0] = pk2(b0.x, b0.y); bp[1] = pk2(b0.z, b0.w);
            bp[2] = pk2(b1.x, b1.y); bp[3] = pk2(b1.z, b1.w);
            #pragma unroll
            for (int i = 0; i < 8; i++)
                #pragma unroll
                for (int jp = 0; jp < 4; jp++)
                    fma2(acc2[i][jp], ap[i], bp[jp]);
        }

        // ---- fold argmin once a k-tile's full dot is accumulated
        if (dc == 7) {
            const int kb = kt * 128;
            float en[8];
            #pragma unroll
            for (int jp = 0; jp < 4; jp++) {
                int c0 = ((jp < 2) ? 0 : 64) + tx * 4 + (jp & 1) * 2;
                en[jp * 2 + 0] = g_enorm[kb + c0];
                en[jp * 2 + 1] = g_enorm[kb + c0 + 1];
            }
            #pragma unroll
            for (int i = 0; i < 8; i++) {
                int   r = (i < 4) ? (ty * 4 + i) : (64 + ty * 4 + (i - 4));
                float A = a_row[r];
                float bk = 3.4e38f; int bc = 0x7fffffff;
                #pragma unroll
                for (int jp = 0; jp < 4; jp++) {
                    int c0 = ((jp < 2) ? 0 : 64) + tx * 4 + (jp & 1) * 2;
                    float mlo, mhi;
                    upk2(mlo, mhi, acc2[i][jp]);
                    acc2[i][jp] = 0ull;
                    // key = fl( fl(A + B) - 2*M ), no contraction
                    float k0 = __fadd_rn(__fadd_rn(A, en[jp * 2 + 0]),
                                         -__fmul_rn(2.0f, mlo));
                    float k1 = __fadd_rn(__fadd_rn(A, en[jp * 2 + 1]),
                                         -__fmul_rn(2.0f, mhi));
                    if (k0 < bk) { bk = k0; bc = kb + c0; }
                    if (k1 < bk) { bk = k1; bc = kb + c0 + 1; }
                }
                #pragma unroll
                for (int m = 8; m; m >>= 1) {
                    float ok = __shfl_xor_sync(0xffffffffu, bk, m);
                    int   oc = __shfl_xor_sync(0xffffffffu, bc, m);
                    if (ok < bk || (ok == bk && oc < bc)) { bk = ok; bc = oc; }
                }
                if (bk < best_key[i] || (bk == best_key[i] && bc < best_k[i])) {
                    best_key[i] = bk; best_k[i] = bc;
                }
            }
        }

        // ---- STS next chunk into the other buffer
        if (c + 1 < 64) {
            float* esn = es + ((c + 1) & 1) * (BK * BN);
            #pragma unroll
            for (int q = 0; q < 4; q++) {
                float vv[4] = {ev[q].x, ev[q].y, ev[q].z, ev[q].w};
                #pragma unroll
                for (int j = 0; j < 4; j++) {
                    int d_l = dd * 4 + j;
                    esn[d_l * BN + ((q * 32 + kk) ^ (d_l & 28))] = vv[j];
                }
            }
        }
        __syncthreads();
    }

    // ---- fused epilogue: gather + straight-through + MSE + histogram
    // all 16 tx lanes hold the reduced (best_key, best_k) for each row i.
    float mse = 0.f;
    #pragma unroll
    for (int i = 0; i < 8; i++) {
        int r = (i < 4) ? (ty * 4 + i) : (64 + ty * 4 + (i - 4));
        int k = best_k[i];
        const float4* xr = (const float4*)x + (rb + r) * (D_DIM / 4);
        const float4* er = (const float4*)e + (size_t)k * (D_DIM / 4);
        float4*       orow = (float4*)out + (rb + r) * (D_DIM / 4);
        #pragma unroll
        for (int q = 0; q < 4; q++) {
            int ii = q * 16 + tx;
            float4 xv = xr[ii];
            float4 qv = er[ii];
            float4 ov;
            float d0 = __fadd_rn(qv.x, -xv.x); ov.x = __fadd_rn(xv.x, d0);
            float d1 = __fadd_rn(qv.y, -xv.y); ov.y = __fadd_rn(xv.y, d1);
            float d2 = __fadd_rn(qv.z, -xv.z); ov.z = __fadd_rn(xv.z, d2);
            float d3 = __fadd_rn(qv.w, -xv.w); ov.w = __fadd_rn(xv.w, d3);
            mse = fmaf(d0, d0, mse); mse = fmaf(d1, d1, mse);
            mse = fmaf(d2, d2, mse); mse = fmaf(d3, d3, mse);
            orow[ii] = ov;
        }
        if (tx == 0) atomicAdd(&g_counts[k], 1u);
    }
    // block reduction of mse -> one double atomic per block
    #pragma unroll
    for (int m = 16; m; m >>= 1) mse += __shfl_xor_sync(0xffffffffu, mse, m);
    int lane = t & 31, w = t >> 5;
    if (lane == 0) redm[w] = mse;
    __syncthreads();
    if (t < 8) {
        float s = redm[t];
        #pragma unroll
        for (int m = 4; m; m >>= 1) s += __shfl_xor_sync(0x000000ffu, s, m);
        if (t == 0) atomicAdd(&g_sumsq, (double)s);
    }
}

// ---------------------------------------------------------------------------
// K4: finalize loss + perplexity
// ---------------------------------------------------------------------------
__global__ void vq_finalize_kernel(float* __restrict__ out_scalars, int n_vec)
{
    __shared__ float red[32];
    const int t = threadIdx.x;           // 1024 threads
    float p = (float)g_counts[t] / (float)n_vec;
    float s = p * logf(p + 1e-10f);
    #pragma unroll
    for (int m = 16; m; m >>= 1) s += __shfl_xor_sync(0xffffffffu, s, m);
    int lane = t & 31, w = t >> 5;
    if (lane == 0) red[w] = s;
    __syncthreads();
    if (t < 32) {
        float t2 = red[t];
        #pragma unroll
        for (int m = 16; m; m >>= 1) t2 += __shfl_xor_sync(0xffffffffu, t2, m);
        if (t == 0) {
            double mse = g_sumsq / ((double)n_vec * (double)D_DIM);
            out_scalars[0] = (float)(1.25 * mse);   // q_latent + 0.25*e_latent
            out_scalars[1] = expf(-t2);
        }
    }
}

// ---------------------------------------------------------------------------
extern "C" void kernel_launch(void* const* d_in, const int* in_sizes, int n_in,
                              void* d_out, int out_size)
{
    const float* x = (const float*)d_in[0];   // [64,32,32,256] f32
    const float* e = (const float*)d_in[1];   // [1024,256] f32
    float* out = (float*)d_out;

    const int n_vec = in_sizes[0] / D_DIM;    // 65536

    static const int kSmem = (D_DIM * BM + 2 * BK * BN) * (int)sizeof(float); // 160 KB
    cudaFuncSetAttribute(vq_argmin_fused_kernel,
                         cudaFuncAttributeMaxDynamicSharedMemorySize, kSmem);

    vq_zero_kernel<<<1, K_CB>>>();
    vq_enorm_kernel<<<K_CB / 8, 256>>>(e);
    vq_argmin_fused_kernel<<<n_vec / BM, NT, kSmem>>>(x, e, out);
    vq_finalize_kernel<<<1, K_CB>>>(out + (size_t)n_vec * D_DIM, n_vec);
}

// round 4
// speedup vs baseline: 1.1202x; 1.0004x over previous
#include <cuda_runtime.h>
#include <math.h>

#define D_DIM 256
#define K_CB  1024

#define BM 128
#define BN 128
#define BK 32
#define NT 256

// ---- scratch (no allocations allowed) ----
__device__ float        g_enorm[K_CB];
__device__ unsigned int g_counts[K_CB];
__device__ double       g_sumsq;

// ---------------------------------------------------------------------------
// packed f32x2 helpers (PTX-only pipe; per-lane IEEE RN identical to fmaf)
// ---------------------------------------------------------------------------
__device__ __forceinline__ unsigned long long pk2(float lo, float hi) {
    unsigned long long r;
    asm("mov.b64 %0, {%1, %2};" : "=l"(r) : "f"(lo), "f"(hi));
    return r;
}
__device__ __forceinline__ void upk2(float& lo, float& hi, unsigned long long v) {
    asm("mov.b64 {%0, %1}, %2;" : "=f"(lo), "=f"(hi) : "l"(v));
}
__device__ __forceinline__ void fma2(unsigned long long& d,
                                     unsigned long long a,
                                     unsigned long long b) {
    asm("fma.rn.f32x2 %0, %1, %2, %0;" : "+l"(d) : "l"(a), "l"(b));
}

// ---------------------------------------------------------------------------
// K0: zero accumulators
// ---------------------------------------------------------------------------
__global__ void vq_zero_kernel() {
    int t = threadIdx.x;
    if (t < K_CB) g_counts[t] = 0u;
    if (t == 0)   g_sumsq = 0.0;
}

// ---------------------------------------------------------------------------
// K1: codebook row norms  g_enorm[k] = sum_d e[k][d]^2   (one warp per row)
// ---------------------------------------------------------------------------
__global__ void vq_enorm_kernel(const float* __restrict__ e) {
    int w    = (blockIdx.x * blockDim.x + threadIdx.x) >> 5;  // row id 0..1023
    int lane = threadIdx.x & 31;
    const float4* e4 = (const float4*)(e + (size_t)w * D_DIM);
    float s = 0.f;
    #pragma unroll
    for (int q = 0; q < 2; q++) {
        float4 v = e4[lane + q * 32];
        s += v.x * v.x + v.y * v.y + v.z * v.z + v.w * v.w;
    }
    #pragma unroll
    for (int m = 16; m; m >>= 1) s += __shfl_xor_sync(0xffffffffu, s, m);
    if (lane == 0) g_enorm[w] = s;
}

// ---------------------------------------------------------------------------
// K2: fused distance-GEMM (f32x2) + argmin + gather/ST output + MSE + hist.
//   M[n][k]: SERIAL ascending-d fma chain per element (f32x2 lanes preserve it)
//   dist = fl( fl(A[n] + B[k]) - 2*M ),  tie-break lowest index.
//   Epilogue: all tx lanes hold the block-row argmin -> cooperative row
//   stream: out = x + (q - x), diff^2 partials, histogram atomics.
// ---------------------------------------------------------------------------
__global__ void __launch_bounds__(NT, 1) vq_argmin_fused_kernel(
    const float* __restrict__ x, const float* __restrict__ e,
    float* __restrict__ out)
{
    extern __shared__ float smem[];
    float* xs = smem;                   // [256][128]
    float* es = smem + D_DIM * BM;      // [2][32][128], xor-swizzled columns
    __shared__ float a_row[BM];         // per-row ||x||^2
    __shared__ float redm[8];

    const int t  = threadIdx.x;
    const int tx = t & 15;
    const int ty = t >> 4;
    const size_t rb = (size_t)blockIdx.x * BM;

    // ---- load x tile transposed: xs[d][m] = x[rb+m][d]
    {
        const float4* x4 = (const float4*)(x + rb * D_DIM);
        #pragma unroll
        for (int it = 0; it < (BM * (D_DIM / 4)) / NT; it++) {
            int i  = t + it * NT;
            int m  = i & (BM - 1);
            int d4 = i >> 7;
            float4 v = x4[(size_t)m * (D_DIM / 4) + d4];
            xs[(d4 * 4 + 0) * BM + m] = v.x;
            xs[(d4 * 4 + 1) * BM + m] = v.y;
            xs[(d4 * 4 + 2) * BM + m] = v.z;
            xs[(d4 * 4 + 3) * BM + m] = v.w;
        }
    }

    const int kk = t >> 3;   // 0..31  (k sub-row)
    const int dd = t & 7;    // 0..7   (float4 column within BK chunk)
    const float4* e4 = (const float4*)e;

    float4 ev[4];
    // prologue: chunk 0 (kt=0, dc=0) -> buf 0
    #pragma unroll
    for (int q = 0; q < 4; q++)
        ev[q] = e4[(size_t)(q * 32 + kk) * (D_DIM / 4) + dd];
    #pragma unroll
    for (int q = 0; q < 4; q++) {
        float vv[4] = {ev[q].x, ev[q].y, ev[q].z, ev[q].w};
        #pragma unroll
        for (int j = 0; j < 4; j++) {
            int d_l = dd * 4 + j;
            es[d_l * BN + ((q * 32 + kk) ^ (d_l & 28))] = vv[j];
        }
    }
    __syncthreads();

    // ---- per-row ||x||^2 (order-free; argmin-invariant low bits)
    if (t < BM) {
        float s0 = 0.f, s1 = 0.f, s2 = 0.f, s3 = 0.f;
        #pragma unroll 8
        for (int d = 0; d < D_DIM; d += 4) {
            float v0 = xs[(d + 0) * BM + t];
            float v1 = xs[(d + 1) * BM + t];
            float v2 = xs[(d + 2) * BM + t];
            float v3 = xs[(d + 3) * BM + t];
            s0 = fmaf(v0, v0, s0); s1 = fmaf(v1, v1, s1);
            s2 = fmaf(v2, v2, s2); s3 = fmaf(v3, v3, s3);
        }
        a_row[t] = (s0 + s1) + (s2 + s3);
    }
    // a_row first read at the c=7 fold; per-iter __syncthreads order it.

    float best_key[8];
    int   best_k[8];
    #pragma unroll
    for (int i = 0; i < 8; i++) { best_key[i] = 3.4e38f; best_k[i] = 0x7fffffff; }

    // packed accumulators: acc2[i][jp] holds cols (pair along j)
    unsigned long long acc2[8][4];
    #pragma unroll
    for (int i = 0; i < 8; i++)
        #pragma unroll
        for (int jp = 0; jp < 4; jp++) acc2[i][jp] = 0ull;

    for (int c = 0; c < 64; c++) {            // 8 k-tiles x 8 d-chunks
        const int kt = c >> 3, dc = c & 7, buf = c & 1;

        // prefetch next chunk into registers
        if (c + 1 < 64) {
            int nkt = (c + 1) >> 3, ndc = (c + 1) & 7;
            #pragma unroll
            for (int q = 0; q < 4; q++)
                ev[q] = e4[(size_t)(nkt * 128 + q * 32 + kk) * (D_DIM / 4)
                           + ndc * 8 + dd];
        }

        // ---- compute: 32 rank-1 updates, packed f32x2 (2 FMA/instr)
        const float* xs_d = xs + (dc * 32) * BM;
        const float* es_d = es + buf * (BK * BN);
        #pragma unroll 4
        for (int d = 0; d < 32; d++) {
            float4 a0 = *(const float4*)(xs_d + d * BM + ty * 4);
            float4 a1 = *(const float4*)(xs_d + d * BM + 64 + ty * 4);
            const int sw = d & 28;
            float4 b0 = *(const float4*)(es_d + d * BN + ((tx * 4) ^ sw));
            float4 b1 = *(const float4*)(es_d + d * BN + (64 + ((tx * 4) ^ sw)));
            unsigned long long ap[8], bp[4];
            ap[0] = pk2(a0.x, a0.x); ap[1] = pk2(a0.y, a0.y);
            ap[2] = pk2(a0.z, a0.z); ap[3] = pk2(a0.w, a0.w);
            ap[4] = pk2(a1.x, a1.x); ap[5] = pk2(a1.y, a1.y);
            ap[6] = pk2(a1.z, a1.z); ap[7] = pk2(a1.w, a1.w);
            bp[0] = pk2(b0.x, b0.y); bp[1] = pk2(b0.z, b0.w);
            bp[2] = pk2(b1.x, b1.y); bp[3] = pk2(b1.z, b1.w);
            #pragma unroll
            for (int i = 0; i < 8; i++)
                #pragma unroll
                for (int jp = 0; jp < 4; jp++)
                    fma2(acc2[i][jp], ap[i], bp[jp]);
        }

        // ---- fold argmin once a k-tile's full dot is accumulated
        if (dc == 7) {
            const int kb = kt * 128;
            float en[8];
            #pragma unroll
            for (int jp = 0; jp < 4; jp++) {
                int c0 = ((jp < 2) ? 0 : 64) + tx * 4 + (jp & 1) * 2;
                en[jp * 2 + 0] = g_enorm[kb + c0];
                en[jp * 2 + 1] = g_enorm[kb + c0 + 1];
            }
            #pragma unroll
            for (int i = 0; i < 8; i++) {
                int   r = (i < 4) ? (ty * 4 + i) : (64 + ty * 4 + (i - 4));
                float A = a_row[r];
                float bk = 3.4e38f; int bc = 0x7fffffff;
                #pragma unroll
                for (int jp = 0; jp < 4; jp++) {
                    int c0 = ((jp < 2) ? 0 : 64) + tx * 4 + (jp & 1) * 2;
                    float mlo, mhi;
                    upk2(mlo, mhi, acc2[i][jp]);
                    acc2[i][jp] = 0ull;
                    // key = fl( fl(A + B) - 2*M ), no contraction
                    float k0 = __fadd_rn(__fadd_rn(A, en[jp * 2 + 0]),
                                         -__fmul_rn(2.0f, mlo));
                    float k1 = __fadd_rn(__fadd_rn(A, en[jp * 2 + 1]),
                                         -__fmul_rn(2.0f, mhi));
                    if (k0 < bk) { bk = k0; bc = kb + c0; }
                    if (k1 < bk) { bk = k1; bc = kb + c0 + 1; }
                }
                #pragma unroll
                for (int m = 8; m; m >>= 1) {
                    float ok = __shfl_xor_sync(0xffffffffu, bk, m);
                    int   oc = __shfl_xor_sync(0xffffffffu, bc, m);
                    if (ok < bk || (ok == bk && oc < bc)) { bk = ok; bc = oc; }
                }
                if (bk < best_key[i] || (bk == best_key[i] && bc < best_k[i])) {
                    best_key[i] = bk; best_k[i] = bc;
                }
            }
        }

        // ---- STS next chunk into the other buffer
        if (c + 1 < 64) {
            float* esn = es + ((c + 1) & 1) * (BK * BN);
            #pragma unroll
            for (int q = 0; q < 4; q++) {
                float vv[4] = {ev[q].x, ev[q].y, ev[q].z, ev[q].w};
                #pragma unroll
                for (int j = 0; j < 4; j++) {
                    int d_l = dd * 4 + j;
                    esn[d_l * BN + ((q * 32 + kk) ^ (d_l & 28))] = vv[j];
                }
            }
        }
        __syncthreads();
    }

    // ---- fused epilogue: gather + straight-through + MSE + histogram
    // all 16 tx lanes hold the reduced (best_key, best_k) for each row i.
    float mse = 0.f;
    #pragma unroll
    for (int i = 0; i < 8; i++) {
        int r = (i < 4) ? (ty * 4 + i) : (64 + ty * 4 + (i - 4));
        int k = best_k[i];
        const float4* xr = (const float4*)x + (rb + r) * (D_DIM / 4);
        const float4* er = (const float4*)e + (size_t)k * (D_DIM / 4);
        float4*       orow = (float4*)out + (rb + r) * (D_DIM / 4);
        #pragma unroll
        for (int q = 0; q < 4; q++) {
            int ii = q * 16 + tx;
            float4 xv = xr[ii];
            float4 qv = er[ii];
            float4 ov;
            float d0 = __fadd_rn(qv.x, -xv.x); ov.x = __fadd_rn(xv.x, d0);
            float d1 = __fadd_rn(qv.y, -xv.y); ov.y = __fadd_rn(xv.y, d1);
            float d2 = __fadd_rn(qv.z, -xv.z); ov.z = __fadd_rn(xv.z, d2);
            float d3 = __fadd_rn(qv.w, -xv.w); ov.w = __fadd_rn(xv.w, d3);
            mse = fmaf(d0, d0, mse); mse = fmaf(d1, d1, mse);
            mse = fmaf(d2, d2, mse); mse = fmaf(d3, d3, mse);
            orow[ii] = ov;
        }
        if (tx == 0) atomicAdd(&g_counts[k], 1u);
    }
    // block reduction of mse -> one double atomic per block
    #pragma unroll
    for (int m = 16; m; m >>= 1) mse += __shfl_xor_sync(0xffffffffu, mse, m);
    int lane = t & 31, w = t >> 5;
    if (lane == 0) redm[w] = mse;
    __syncthreads();
    if (t < 8) {
        float s = redm[t];
        #pragma unroll
        for (int m = 4; m; m >>= 1) s += __shfl_xor_sync(0x000000ffu, s, m);
        if (t == 0) atomicAdd(&g_sumsq, (double)s);
    }
}

// ---------------------------------------------------------------------------
// K4: finalize loss + perplexity
// ---------------------------------------------------------------------------
__global__ void vq_finalize_kernel(float* __restrict__ out_scalars, int n_vec)
{
    __shared__ float red[32];
    const int t = threadIdx.x;           // 1024 threads
    float p = (float)g_counts[t] / (float)n_vec;
    float s = p * logf(p + 1e-10f);
    #pragma unroll
    for (int m = 16; m; m >>= 1) s += __shfl_xor_sync(0xffffffffu, s, m);
    int lane = t & 31, w = t >> 5;
    if (lane == 0) red[w] = s;
    __syncthreads();
    if (t < 32) {
        float t2 = red[t];
        #pragma unroll
        for (int m = 16; m; m >>= 1) t2 += __shfl_xor_sync(0xffffffffu, t2, m);
        if (t == 0) {
            double mse = g_sumsq / ((double)n_vec * (double)D_DIM);
            out_scalars[0] = (float)(1.25 * mse);   // q_latent + 0.25*e_latent
            out_scalars[1] = expf(-t2);
        }
    }
}

// ---------------------------------------------------------------------------
extern "C" void kernel_launch(void* const* d_in, const int* in_sizes, int n_in,
                              void* d_out, int out_size)
{
    const float* x = (const float*)d_in[0];   // [64,32,32,256] f32
    const float* e = (const float*)d_in[1];   // [1024,256] f32
    float* out = (float*)d_out;

    const int n_vec = in_sizes[0] / D_DIM;    // 65536

    static const int kSmem = (D_DIM * BM + 2 * BK * BN) * (int)sizeof(float); // 160 KB
    cudaFuncSetAttribute(vq_argmin_fused_kernel,
                         cudaFuncAttributeMaxDynamicSharedMemorySize, kSmem);

    vq_zero_kernel<<<1, K_CB>>>();
    vq_enorm_kernel<<<K_CB / 8, 256>>>(e);
    vq_argmin_fused_kernel<<<n_vec / BM, NT, kSmem>>>(x, e, out);
    vq_finalize_kernel<<<1, K_CB>>>(out + (size_t)n_vec * D_DIM, n_vec);
}